// round 4
// baseline (speedup 1.0000x reference)
#include <cuda_runtime.h>

#define TT 64
#define BB 256
#define DD 512

// pre-activations, K2-block-contiguous layout:
// g_pre2[bblk(64)][t(64)][bloc(4)][gate(4)][q(6)]
__device__ __align__(16) float g_pre2[TT * BB * 24];

// ---------------------------------------------------------------------------
// K1: pre[t,b,g,q] = inputs[t,b,:] @ Wg[:512,q] + bg[q] + theta_g[q]
// grid 128 x 256; block = 128 rows. warp w: gate = w&3, row-half = w>>2;
// lane owns 2 adjacent rows. Scalar FFMA (FFMA2 regressed: RF-bank rt=3).
// ---------------------------------------------------------------------------
__global__ void __launch_bounds__(256, 1) k1_gemm(
    const float* __restrict__ X,
    const float* __restrict__ Wf, const float* __restrict__ bf,
    const float* __restrict__ Wi, const float* __restrict__ bi,
    const float* __restrict__ Wu, const float* __restrict__ bu,
    const float* __restrict__ Wo, const float* __restrict__ bo,
    const float* __restrict__ thf, const float* __restrict__ thi,
    const float* __restrict__ thu, const float* __restrict__ tho)
{
    __shared__ float Wph[256 * 24];   // K-half of W, [dd][g*6+q]
    __shared__ float Xsh[32 * 130];   // x tile transposed [d][row]

    const int tid  = threadIdx.x;
    const int warp = tid >> 5;
    const int lane = tid & 31;
    const int gate = warp & 3;
    const int rloc = ((warp >> 2) << 6) + (lane << 1);   // block-local row (even)
    const int rowbase = blockIdx.x << 7;

    const float* bg = (gate == 0) ? bf  : (gate == 1) ? bi  : (gate == 2) ? bu  : bo;
    const float* tg = (gate == 0) ? thf : (gate == 1) ? thi : (gate == 2) ? thu : tho;

    float acc0[6], acc1[6];
#pragma unroll
    for (int q = 0; q < 6; q++) {
        float bias = __ldg(bg + q) + __ldg(tg + q);   // fold theta into bias
        acc0[q] = bias;
        acc1[q] = bias;
    }

    const int cc = tid & 7;   // d-group for staging
    const int rr = tid >> 3;  // row for staging

    for (int kh = 0; kh < 2; kh++) {
        __syncthreads();
#pragma unroll
        for (int k = 0; k < 24; k++) {
            int idx = tid + (k << 8);          // dd*24 + col
            int dd  = idx / 24;
            int col = idx - dd * 24;
            int g2  = col / 6;
            int q2  = col - g2 * 6;
            const float* Ws = (g2 == 0) ? Wf : (g2 == 1) ? Wi : (g2 == 2) ? Wu : Wo;
            Wph[idx] = Ws[((kh << 8) + dd) * 6 + q2];
        }
        for (int tile = 0; tile < 8; tile++) {
            const int d0 = (kh << 8) + (tile << 5);
            __syncthreads();
#pragma unroll
            for (int p = 0; p < 4; p++) {
                int r = rr + (p << 5);
                const float4 v = *reinterpret_cast<const float4*>(
                    X + (size_t)(rowbase + r) * DD + d0 + (cc << 2));
                Xsh[((cc << 2) + 0) * 130 + r] = v.x;
                Xsh[((cc << 2) + 1) * 130 + r] = v.y;
                Xsh[((cc << 2) + 2) * 130 + r] = v.z;
                Xsh[((cc << 2) + 3) * 130 + r] = v.w;
            }
            __syncthreads();
#pragma unroll
            for (int d = 0; d < 32; d++) {
                const int dd = (tile << 5) + d;
                const float2 w01 = *reinterpret_cast<const float2*>(&Wph[dd * 24 + gate * 6 + 0]);
                const float2 w23 = *reinterpret_cast<const float2*>(&Wph[dd * 24 + gate * 6 + 2]);
                const float2 w45 = *reinterpret_cast<const float2*>(&Wph[dd * 24 + gate * 6 + 4]);
                const float2 x2  = *reinterpret_cast<const float2*>(&Xsh[d * 130 + rloc]);
                acc0[0] = fmaf(x2.x, w01.x, acc0[0]);
                acc0[1] = fmaf(x2.x, w01.y, acc0[1]);
                acc0[2] = fmaf(x2.x, w23.x, acc0[2]);
                acc0[3] = fmaf(x2.x, w23.y, acc0[3]);
                acc0[4] = fmaf(x2.x, w45.x, acc0[4]);
                acc0[5] = fmaf(x2.x, w45.y, acc0[5]);
                acc1[0] = fmaf(x2.y, w01.x, acc1[0]);
                acc1[1] = fmaf(x2.y, w01.y, acc1[1]);
                acc1[2] = fmaf(x2.y, w23.x, acc1[2]);
                acc1[3] = fmaf(x2.y, w23.y, acc1[3]);
                acc1[4] = fmaf(x2.y, w45.x, acc1[4]);
                acc1[5] = fmaf(x2.y, w45.y, acc1[5]);
            }
        }
    }

    // row = t*BB + b ; store to K2-block-contiguous layout (4 batches/block)
    const int t = rowbase >> 8;
    const int b = (rowbase & 255) + rloc;       // even
    float* dst = g_pre2 + ((size_t)((b >> 2) * TT + t) * 96) + (b & 3) * 24 + gate * 6;
    *reinterpret_cast<float2*>(dst + 0)      = make_float2(acc0[0], acc0[1]);
    *reinterpret_cast<float2*>(dst + 2)      = make_float2(acc0[2], acc0[3]);
    *reinterpret_cast<float2*>(dst + 4)      = make_float2(acc0[4], acc0[5]);
    *reinterpret_cast<float2*>(dst + 24 + 0) = make_float2(acc1[0], acc1[1]);
    *reinterpret_cast<float2*>(dst + 24 + 2) = make_float2(acc1[2], acc1[3]);
    *reinterpret_cast<float2*>(dst + 24 + 4) = make_float2(acc1[4], acc1[5]);
}

// ---------------------------------------------------------------------------
// K2: LSTM scan. grid 64 x 128. One WARP per batch; lane = gate*6+q, 24 live
// lanes; lanes 24-31 are clamped to in-range addresses (results unused).
// Per step the warp issues only 5 MUFU instructions (1 cos, 2 exp, 2 rcp).
// qlayer(a)[0] = z1..z5 ; qlayer(a)[k] = z0..zk, z = cos(a).
// ---------------------------------------------------------------------------
__global__ void __launch_bounds__(128, 1) k2_scan(
    const float* __restrict__ Wf, const float* __restrict__ Wi,
    const float* __restrict__ Wu, const float* __restrict__ Wo,
    float* __restrict__ out)
{
    __shared__ float ps[TT * 96];    // 24576 B : [t][bloc(4)][gate][q]

    const int tid  = threadIdx.x;
    const int wrp  = tid >> 5;
    const int lane = tid & 31;

    // cooperative stage of this block's 4 batches of pre (coalesced float4)
    {
        const float4* src = reinterpret_cast<const float4*>(g_pre2 + (size_t)blockIdx.x * (TT * 96));
        float4* dst = reinterpret_cast<float4*>(ps);
#pragma unroll
        for (int i = 0; i < (TT * 96) / 4 / 128; i++)
            dst[tid + i * 128] = src[tid + i * 128];
    }
    __syncthreads();

    const bool live = (lane < 24);
    const int lc = live ? lane : 0;               // clamped lane for addressing
    const int b  = (blockIdx.x << 2) + wrp;       // this warp's batch
    const int g  = lc / 6;                        // gate
    const int q  = lc - g * 6;                    // wire
    const int gb = g * 6;                         // gate group base lane
    const float* Wg = (g == 1) ? Wi : (g == 2) ? Wu : (g == 3) ? Wo : Wf;
    const bool isU  = (g == 2);
    const float cmul = isU ? -2.0f : -1.0f;       // exp argument scale

    // recurrent weights for this lane's (gate, q): Wh[j] = Wg[512+j][q]
    float wh0 = __ldg(Wg + (DD + 0) * 6 + q);
    float wh1 = __ldg(Wg + (DD + 1) * 6 + q);
    float wh2 = __ldg(Wg + (DD + 2) * 6 + q);
    float wh3 = __ldg(Wg + (DD + 3) * 6 + q);
    float wh4 = __ldg(Wg + (DD + 4) * 6 + q);
    float wh5 = __ldg(Wg + (DD + 5) * 6 + q);

    float h0 = 0.f, h1 = 0.f, h2 = 0.f, h3 = 0.f, h4 = 0.f, h5 = 0.f;
    float cq = 0.f;                                // owner lanes 0..5 hold c[q]

    const unsigned mask = 0xffffffffu;
    const float* pb = ps + wrp * 24 + lc;

#pragma unroll 2
    for (int t = 0; t < TT; t++) {
        const float p = pb[t * 96];                // LDS, conflict-free

        // a = p + h @ Wh (tree: two partials)
        float d0 = fmaf(h2, wh2, fmaf(h1, wh1, fmaf(h0, wh0, p)));
        float d1 = fmaf(h3, wh3, fmaf(h4, wh4, h5 * wh5));
        float a  = d0 + d1;

        float z = __cosf(a);

        // gather gate group's z (independent shfls, one hop)
        float z0 = __shfl_sync(mask, z, gb + 0);
        float z1 = __shfl_sync(mask, z, gb + 1);
        float z2 = __shfl_sync(mask, z, gb + 2);
        float z3 = __shfl_sync(mask, z, gb + 3);
        float z4 = __shfl_sync(mask, z, gb + 4);
        float z5 = __shfl_sync(mask, z, gb + 5);

        // entanglement products, select own by q
        float t01 = z0 * z1, t12 = z1 * z2, t23 = z2 * z3, t34 = z3 * z4, t45 = z4 * z5;
        float P3  = t01 * t23;
        float w0  = t12 * (t34 * z5);
        float w2  = t01 * z2;
        float w4  = P3 * z4;
        float w5  = P3 * t45;
        float wv  = (q == 0) ? w0 : (q == 1) ? t01 : (q == 2) ? w2
                  : (q == 3) ? P3 : (q == 4) ? w4 : w5;

        // f,i,o: sigmoid(wv); u: tanh(wv) = 2*sigmoid(2*wv)-1
        float e = __expf(cmul * wv);
        float s = __fdividef(1.0f, 1.0f + e);
        float v = isU ? fmaf(2.0f, s, -1.0f) : s;

        // owner lanes (l<6) gather the 4 gates' values for wire l
        float fq = __shfl_sync(mask, v, lc);
        float iq = __shfl_sync(mask, v, lc + 6);
        float uq = __shfl_sync(mask, v, lc + 12);
        float oq = __shfl_sync(mask, v, lc + 18);

        float cn = fmaf(fq, cq, iq * uq);
        cq = cn;
        float e2 = __expf(-2.0f * cn);
        float s2 = __fdividef(1.0f, 1.0f + e2);
        float th = fmaf(2.0f, s2, -1.0f);          // tanh(cn)
        float hq = oq * th;

        if (lane < 6)
            out[((size_t)t * BB + b) * 6 + lane] = hq;

        // broadcast h to all lanes for next step's dot
        h0 = __shfl_sync(mask, hq, 0);
        h1 = __shfl_sync(mask, hq, 1);
        h2 = __shfl_sync(mask, hq, 2);
        h3 = __shfl_sync(mask, hq, 3);
        h4 = __shfl_sync(mask, hq, 4);
        h5 = __shfl_sync(mask, hq, 5);
    }

    if (lane < 6) {
        float hfin = (lane == 0) ? h0 : (lane == 1) ? h1 : (lane == 2) ? h2
                   : (lane == 3) ? h3 : (lane == 4) ? h4 : h5;
        float* hx = out + (size_t)TT * BB * 6 + (size_t)b * 6 + lane;
        hx[0]      = hfin;
        hx[BB * 6] = cq;
    }
}

extern "C" void kernel_launch(void* const* d_in, const int* in_sizes, int n_in,
                              void* d_out, int out_size)
{
    const float* X   = (const float*)d_in[0];
    const float* Wf  = (const float*)d_in[1];
    const float* bf  = (const float*)d_in[2];
    const float* Wi  = (const float*)d_in[3];
    const float* bi  = (const float*)d_in[4];
    const float* Wu  = (const float*)d_in[5];
    const float* bu  = (const float*)d_in[6];
    const float* Wo  = (const float*)d_in[7];
    const float* bo  = (const float*)d_in[8];
    const float* thf = (const float*)d_in[9];
    const float* thi = (const float*)d_in[10];
    const float* thu = (const float*)d_in[11];
    const float* tho = (const float*)d_in[12];
    float* out = (float*)d_out;

    k1_gemm<<<128, 256>>>(X, Wf, bf, Wi, bi, Wu, bu, Wo, bo, thf, thi, thu, tho);
    k2_scan<<<64, 128>>>(Wf, Wi, Wu, Wo, out);
}

// round 5
// speedup vs baseline: 1.1223x; 1.1223x over previous
#include <cuda_runtime.h>

#define TT 64
#define BB 256
#define DD 512

// pre-activations, t-major (proven fast K1 store): g_pre[row][gate][q], row = t*BB+b
__device__ __align__(16) float g_pre[TT * BB * 24];

// ---------------------------------------------------------------------------
// K1: pre[t,b,g,q] = inputs[t,b,:] @ Wg[:512,q] + bg[q] + theta_g[q]
// EXACT R1 kernel (measured fastest): scalar FFMA, t-major store.
// ---------------------------------------------------------------------------
__global__ void __launch_bounds__(256, 1) k1_gemm(
    const float* __restrict__ X,
    const float* __restrict__ Wf, const float* __restrict__ bf,
    const float* __restrict__ Wi, const float* __restrict__ bi,
    const float* __restrict__ Wu, const float* __restrict__ bu,
    const float* __restrict__ Wo, const float* __restrict__ bo,
    const float* __restrict__ thf, const float* __restrict__ thi,
    const float* __restrict__ thu, const float* __restrict__ tho)
{
    __shared__ float Wph[256 * 24];   // K-half of W, [dd][g*6+q]
    __shared__ float Xsh[32 * 130];   // x tile transposed [d][row]

    const int tid  = threadIdx.x;
    const int warp = tid >> 5;
    const int lane = tid & 31;
    const int gate = warp & 3;
    const int rloc = ((warp >> 2) << 6) + (lane << 1);   // block-local row (even)
    const int rowbase = blockIdx.x << 7;

    const float* bg = (gate == 0) ? bf  : (gate == 1) ? bi  : (gate == 2) ? bu  : bo;
    const float* tg = (gate == 0) ? thf : (gate == 1) ? thi : (gate == 2) ? thu : tho;

    float acc0[6], acc1[6];
#pragma unroll
    for (int q = 0; q < 6; q++) {
        float bias = __ldg(bg + q) + __ldg(tg + q);   // fold theta into bias
        acc0[q] = bias;
        acc1[q] = bias;
    }

    const int cc = tid & 7;
    const int rr = tid >> 3;

    for (int kh = 0; kh < 2; kh++) {
        __syncthreads();
#pragma unroll
        for (int k = 0; k < 24; k++) {
            int idx = tid + (k << 8);
            int dd  = idx / 24;
            int col = idx - dd * 24;
            int g2  = col / 6;
            int q2  = col - g2 * 6;
            const float* Ws = (g2 == 0) ? Wf : (g2 == 1) ? Wi : (g2 == 2) ? Wu : Wo;
            Wph[idx] = Ws[((kh << 8) + dd) * 6 + q2];
        }
        for (int tile = 0; tile < 8; tile++) {
            const int d0 = (kh << 8) + (tile << 5);
            __syncthreads();
#pragma unroll
            for (int p = 0; p < 4; p++) {
                int r = rr + (p << 5);
                const float4 v = *reinterpret_cast<const float4*>(
                    X + (size_t)(rowbase + r) * DD + d0 + (cc << 2));
                Xsh[((cc << 2) + 0) * 130 + r] = v.x;
                Xsh[((cc << 2) + 1) * 130 + r] = v.y;
                Xsh[((cc << 2) + 2) * 130 + r] = v.z;
                Xsh[((cc << 2) + 3) * 130 + r] = v.w;
            }
            __syncthreads();
#pragma unroll
            for (int d = 0; d < 32; d++) {
                const int dd = (tile << 5) + d;
                const float2 w01 = *reinterpret_cast<const float2*>(&Wph[dd * 24 + gate * 6 + 0]);
                const float2 w23 = *reinterpret_cast<const float2*>(&Wph[dd * 24 + gate * 6 + 2]);
                const float2 w45 = *reinterpret_cast<const float2*>(&Wph[dd * 24 + gate * 6 + 4]);
                const float2 x2  = *reinterpret_cast<const float2*>(&Xsh[d * 130 + rloc]);
                acc0[0] = fmaf(x2.x, w01.x, acc0[0]);
                acc0[1] = fmaf(x2.x, w01.y, acc0[1]);
                acc0[2] = fmaf(x2.x, w23.x, acc0[2]);
                acc0[3] = fmaf(x2.x, w23.y, acc0[3]);
                acc0[4] = fmaf(x2.x, w45.x, acc0[4]);
                acc0[5] = fmaf(x2.x, w45.y, acc0[5]);
                acc1[0] = fmaf(x2.y, w01.x, acc1[0]);
                acc1[1] = fmaf(x2.y, w01.y, acc1[1]);
                acc1[2] = fmaf(x2.y, w23.x, acc1[2]);
                acc1[3] = fmaf(x2.y, w23.y, acc1[3]);
                acc1[4] = fmaf(x2.y, w45.x, acc1[4]);
                acc1[5] = fmaf(x2.y, w45.y, acc1[5]);
            }
        }
    }

    float* dst = g_pre + (size_t)(rowbase + rloc) * 24 + gate * 6;
    *reinterpret_cast<float2*>(dst + 0)      = make_float2(acc0[0], acc0[1]);
    *reinterpret_cast<float2*>(dst + 2)      = make_float2(acc0[2], acc0[3]);
    *reinterpret_cast<float2*>(dst + 4)      = make_float2(acc0[4], acc0[5]);
    *reinterpret_cast<float2*>(dst + 24 + 0) = make_float2(acc1[0], acc1[1]);
    *reinterpret_cast<float2*>(dst + 24 + 2) = make_float2(acc1[2], acc1[3]);
    *reinterpret_cast<float2*>(dst + 24 + 4) = make_float2(acc1[4], acc1[5]);
}

// tanh via degree-9 odd Taylor, valid |u| <= 0.52 (err <= ~7e-6)
__device__ __forceinline__ float tanh_poly(float u) {
    float s = u * u;
    float p = fmaf(s, 0.021869488f, -0.053968254f);   // 62/2835, -17/315
    p = fmaf(s, p, 0.13333333f);                      // 2/15
    p = fmaf(s, p, -0.33333333f);                     // -1/3
    return fmaf(s * u, p, u);
}

// ---------------------------------------------------------------------------
// K2: LSTM scan. grid 32 x 128. 4 warps stage 48KB of pre into SMEM (from
// t-major layout, 768B contiguous per (t, 8-batch) chunk); warp 0 scans.
// lane = (batch-in-block<<2)|gate ; h,c replicated across the 4 gate lanes
// (single shuffle hop per step). MUFU only: 6 cos + 18 rcp; sigmoid/tanh via
// bounded polynomials (|w|<=1, |c|<=2.075 guaranteed by the gate structure).
// ---------------------------------------------------------------------------
__global__ void __launch_bounds__(128, 1) k2_scan(
    const float* __restrict__ Wf, const float* __restrict__ Wi,
    const float* __restrict__ Wu, const float* __restrict__ Wo,
    float* __restrict__ out)
{
    __shared__ float ps[TT * 192];    // 48KB : [t][bloc(8)][gate][q]

    const int tid = threadIdx.x;
    const int b0  = blockIdx.x << 3;

    // stage from t-major g_pre: per t, rows b0..b0+7 are 192 floats contiguous
    {
        const float4* src = reinterpret_cast<const float4*>(g_pre);
        float4* dst = reinterpret_cast<float4*>(ps);
#pragma unroll
        for (int k = 0; k < 24; k++) {
            int i = tid + (k << 7);          // 0..3071
            int t = i / 48;
            int c = i - t * 48;
            dst[t * 48 + c] = src[(size_t)(t * BB + b0) * 6 + c];
        }
    }
    __syncthreads();
    if (tid >= 32) return;

    const int lane = tid;
    const int g    = lane & 3;
    const int bl   = lane >> 2;
    const int b    = b0 + bl;
    const float* Wg = (g == 0) ? Wf : (g == 1) ? Wi : (g == 2) ? Wu : Wo;

    float Wh[36];
#pragma unroll
    for (int j = 0; j < 6; j++)
#pragma unroll
        for (int q = 0; q < 6; q++)
            Wh[j * 6 + q] = __ldg(Wg + (DD + j) * 6 + q);

    float h[6], c[6];
#pragma unroll
    for (int q = 0; q < 6; q++) { h[q] = 0.0f; c[q] = 0.0f; }

    const float* pb = ps + bl * 24 + g * 6;
    const unsigned mask = 0xffffffffu;
    const int qb = lane & ~3;
    const bool isU = (g == 2);

#pragma unroll 2
    for (int t = 0; t < TT; t++) {
        const float2 p0 = *reinterpret_cast<const float2*>(pb + t * 192 + 0);
        const float2 p1 = *reinterpret_cast<const float2*>(pb + t * 192 + 2);
        const float2 p2 = *reinterpret_cast<const float2*>(pb + t * 192 + 4);
        float p[6] = { p0.x, p0.y, p1.x, p1.y, p2.x, p2.y };

        // a[q] = p[q] + h @ Wh (two parallel partials)
        float a[6];
#pragma unroll
        for (int q = 0; q < 6; q++) {
            float u0 = fmaf(h[2], Wh[2 * 6 + q], fmaf(h[1], Wh[1 * 6 + q], fmaf(h[0], Wh[0 * 6 + q], p[q])));
            float u1 = fmaf(h[3], Wh[3 * 6 + q], fmaf(h[4], Wh[4 * 6 + q], h[5] * Wh[5 * 6 + q]));
            a[q] = u0 + u1;
        }

        float z[6];
#pragma unroll
        for (int q = 0; q < 6; q++) z[q] = __cosf(a[q]);

        // entanglement products (tree)
        float z01 = z[0] * z[1];
        float z23 = z[2] * z[3];
        float z45 = z[4] * z[5];
        float w[6];
        w[1] = z01;
        w[2] = z01 * z[2];
        w[3] = z01 * z23;
        w[4] = w[3] * z[4];
        w[5] = w[3] * z45;
        w[0] = z[1] * (z23 * z45);

        // v: f,i,o = sigmoid(w) = 0.5 + 0.5*tanh(w/2); u = tanh(w) = 2t/(1+t^2)
        float v[6];
#pragma unroll
        for (int q = 0; q < 6; q++) {
            float tq  = tanh_poly(0.5f * w[q]);        // |w/2| <= 0.5
            float den = fmaf(tq, tq, 1.0f);
            float vt  = __fdividef(tq + tq, den);      // tanh(w), 1 rcp
            v[q] = isU ? vt : fmaf(0.5f, tq, 0.5f);
        }

        // gather the 4 gates' values per wire, update c/h (replicated)
#pragma unroll
        for (int q = 0; q < 6; q++) {
            float fq = __shfl_sync(mask, v[q], qb + 0);
            float iq = __shfl_sync(mask, v[q], qb + 1);
            float uq = __shfl_sync(mask, v[q], qb + 2);
            float oq = __shfl_sync(mask, v[q], qb + 3);
            float cn = fmaf(fq, c[q], iq * uq);
            c[q] = cn;
            // tanh(cn), |cn| <= 2.075: t=tanh(cn/4) poly, then two doublings
            float t1 = tanh_poly(0.25f * cn);
            float d1 = fmaf(t1, t1, 1.0f);
            float t2 = __fdividef(t1 + t1, d1);        // tanh(cn/2)
            float d2 = fmaf(t2, t2, 1.0f);
            float th = __fdividef(t2 + t2, d2);        // tanh(cn)
            h[q] = oq * th;
        }

        if (g == 0) {
            float* o0 = out + ((size_t)t * BB + b) * 6;
            *reinterpret_cast<float2*>(o0 + 0) = make_float2(h[0], h[1]);
            *reinterpret_cast<float2*>(o0 + 2) = make_float2(h[2], h[3]);
            *reinterpret_cast<float2*>(o0 + 4) = make_float2(h[4], h[5]);
        }
    }

    if (g == 0) {
        float* hx = out + (size_t)TT * BB * 6 + (size_t)b * 6;
        float* cx = hx + BB * 6;
        *reinterpret_cast<float2*>(hx + 0) = make_float2(h[0], h[1]);
        *reinterpret_cast<float2*>(hx + 2) = make_float2(h[2], h[3]);
        *reinterpret_cast<float2*>(hx + 4) = make_float2(h[4], h[5]);
        *reinterpret_cast<float2*>(cx + 0) = make_float2(c[0], c[1]);
        *reinterpret_cast<float2*>(cx + 2) = make_float2(c[2], c[3]);
        *reinterpret_cast<float2*>(cx + 4) = make_float2(c[4], c[5]);
    }
}

extern "C" void kernel_launch(void* const* d_in, const int* in_sizes, int n_in,
                              void* d_out, int out_size)
{
    const float* X   = (const float*)d_in[0];
    const float* Wf  = (const float*)d_in[1];
    const float* bf  = (const float*)d_in[2];
    const float* Wi  = (const float*)d_in[3];
    const float* bi  = (const float*)d_in[4];
    const float* Wu  = (const float*)d_in[5];
    const float* bu  = (const float*)d_in[6];
    const float* Wo  = (const float*)d_in[7];
    const float* bo  = (const float*)d_in[8];
    const float* thf = (const float*)d_in[9];
    const float* thi = (const float*)d_in[10];
    const float* thu = (const float*)d_in[11];
    const float* tho = (const float*)d_in[12];
    float* out = (float*)d_out;

    k1_gemm<<<128, 256>>>(X, Wf, bf, Wi, bi, Wu, bu, Wo, bo, thf, thi, thu, tho);
    k2_scan<<<32, 128>>>(Wf, Wi, Wu, Wo, out);
}